// round 8
// baseline (speedup 1.0000x reference)
#include <cuda_runtime.h>

// Problem constants (fixed by setup_inputs)
#define T_   48
#define BS_  256
#define V_   4096
#define K_   32
#define U2_  64      // 2*K
#define RIDS_ 1024
#define NCHUNK 4     // V / 1024
#define TBATCH 6     // t-steps per load batch (12 LDG.128 in flight)
#define EPSF 1e-9f

// accumulator slots
#define A_SEL_NUM 0
#define A_SEL_DEN 1
#define A_ID_NUM  2
#define A_ID_DEN  3
#define A_RATE    4
#define A_ENT     5
#define A_SMOOTH  6
#define A_LEN     7
#define A_KL      8
#define NACC      9

// Scratch (device globals — no allocation allowed).
__device__ float g_ptrue4  [NCHUNK * T_ * BS_];  // per (chunk,t,b) partial dot
__device__ float g_stepsum4[NCHUNK * T_ * BS_];  // per (chunk,t,b) partial label-sum
__device__ float g_distr   [BS_ * V_];           // dist_r[b,v] = sum_t out_ids[t,b,v]
__device__ float g_part    [NACC * BS_];         // per-batch loss partials
// last-arriver counters (self-resetting each launch; zero-init at load)
__device__ unsigned int g_cnt[BS_];
__device__ unsigned int g_done;

// ---------------------------------------------------------------------------
// Fused kernel: streaming pass + per-batch KL/epilogue (last chunk-arriver)
// + final combine (last batch-arriver). grid (NCHUNK, BS), 256 threads.
// ---------------------------------------------------------------------------
__global__ void __launch_bounds__(256) fused_loss(
    const float* __restrict__ out_ids,
    const float* __restrict__ trg_labels,
    const int*   __restrict__ candi_ids,
    const float* __restrict__ sel_probs,
    const int*   __restrict__ routes,
    const float* __restrict__ sel_onehot,
    const float* __restrict__ out_rates,   // [T,BS]
    const float* __restrict__ trg_rates,   // [T+2,BS]
    const int*   __restrict__ trg_lengths, // [BS]
    float* __restrict__ d_out)
{
    __shared__ float s_dot[T_][8];   // [t][warp]
    __shared__ float s_ls [T_][8];
    __shared__ unsigned int s_last, s_fin;
    // KL-phase smem
    __shared__ int   tbl[RIDS_];
    __shared__ int   ids_s[U2_];
    __shared__ float probs_s[U2_];
    __shared__ float Pm[U2_];
    __shared__ float agg[U2_];
    __shared__ float wpart[7][8];

    const int b    = blockIdx.y;
    const int tid  = threadIdx.x;
    const int v0   = blockIdx.x * 1024 + tid * 4;
    const int lane = tid & 31;
    const int warp = tid >> 5;

    // ===================== Phase 1: streaming =====================
    float4 dist = make_float4(0.f, 0.f, 0.f, 0.f);

    #pragma unroll 1
    for (int t0 = 0; t0 < T_; t0 += TBATCH) {
        float4 o[TBATCH], l[TBATCH];
        #pragma unroll
        for (int j = 0; j < TBATCH; j++) {
            int t = t0 + j;
            o[j] = *(const float4*)(out_ids    + ((t    ) * BS_ + b) * V_ + v0);
            l[j] = *(const float4*)(trg_labels + ((t + 1) * BS_ + b) * V_ + v0);
        }
        #pragma unroll
        for (int j = 0; j < TBATCH; j++) {
            int t = t0 + j;
            dist.x += o[j].x; dist.y += o[j].y; dist.z += o[j].z; dist.w += o[j].w;
            float dot = o[j].x * l[j].x + o[j].y * l[j].y +
                        o[j].z * l[j].z + o[j].w * l[j].w;
            float ls  = l[j].x + l[j].y + l[j].z + l[j].w;
            #pragma unroll
            for (int off = 16; off > 0; off >>= 1) {
                dot += __shfl_down_sync(0xffffffffu, dot, off);
                ls  += __shfl_down_sync(0xffffffffu, ls,  off);
            }
            if (lane == 0) { s_dot[t][warp] = dot; s_ls[t][warp] = ls; }
        }
    }
    *(float4*)(g_distr + b * V_ + v0) = dist;

    __syncthreads();
    const int chunkOff = blockIdx.x * (T_ * BS_);
    for (int idx = tid; idx < T_ * 2; idx += 256) {
        int t = idx >> 1;
        const float* src = (idx & 1) ? s_ls[t] : s_dot[t];
        float v = src[0] + src[1] + src[2] + src[3] +
                  src[4] + src[5] + src[6] + src[7];
        float* dst = (idx & 1) ? &g_stepsum4[chunkOff + t * BS_ + b]
                               : &g_ptrue4  [chunkOff + t * BS_ + b];
        *dst = v;
    }
    __syncthreads();

    // release our writes, count chunk arrivals for batch b
    if (tid == 0) {
        __threadfence();
        s_last = (atomicAdd(&g_cnt[b], 1u) == NCHUNK - 1) ? 1u : 0u;
    }
    __syncthreads();
    if (!s_last) return;

    // ============ Phase 2: KL + epilogue for batch b (last arriver) ============
    if (tid == 0) __threadfence();   // acquire other chunks' writes
    __syncthreads();

    for (int i = tid; i < RIDS_; i += 256) tbl[i] = U2_;
    if (tid < U2_) {
        ids_s[tid]   = candi_ids[b * U2_ + tid];
        probs_s[tid] = sel_probs[b * U2_ + tid];
        Pm[tid]  = 0.f;
        agg[tid] = 0.f;
    }
    __syncthreads();

    if (tid < U2_) atomicMin(&tbl[ids_s[tid]], tid);
    __syncthreads();

    if (tid < U2_) atomicAdd(&Pm[tbl[ids_s[tid]]], probs_s[tid]);
    __syncthreads();

    // project route mass onto union slots
    for (int v = tid; v < V_; v += 256) {
        int r = routes[b * V_ + v];
        int slot = tbl[r];
        if (slot < U2_) atomicAdd(&agg[slot], g_distr[b * V_ + v]);
    }

    // per-batch epilogue terms
    const int len = trg_lengths[b];
    float id_num = 0.f, id_den = 0.f, rate_num = 0.f, smooth = 0.f;
    float ent = 0.f, sel_num = 0.f, sel_den = 0.f;

    for (int t = tid; t < T_; t += 256) {
        float pt = 0.f, ss = 0.f;
        #pragma unroll
        for (int c = 0; c < NCHUNK; c++) {
            pt += g_ptrue4  [c * (T_ * BS_) + t * BS_ + b];
            ss += g_stepsum4[c * (T_ * BS_) + t * BS_ + b];
        }
        float m = (ss > 0.5f) ? 1.f : 0.f;
        id_num += -logf(fmaxf(pt, EPSF)) * m;
        id_den += m;
        float orv = out_rates[t * BS_ + b];
        rate_num += fabsf(orv - trg_rates[(t + 1) * BS_ + b]);
        if (t < T_ - 1 && t < len - 3)
            smooth += fabsf(out_rates[(t + 1) * BS_ + b] - orv);
    }

    if (tid < U2_) {
        float p = fmaxf(probs_s[tid], EPSF);
        ent = -p * logf(p);
    }

    if (tid < 2) {
        float pt = 0.f, ms = 0.f;
        const float* oh = sel_onehot + (b * 2 + tid) * K_;
        const float* pp = probs_s + tid * K_;
        #pragma unroll 8
        for (int k = 0; k < K_; k++) { pt += pp[k] * oh[k]; ms += oh[k]; }
        float m = (ms > 0.5f) ? 1.f : 0.f;
        sel_num = -logf(fmaxf(pt, EPSF)) * m;
        sel_den = m;
    }

    float vals[7] = {sel_num, sel_den, id_num, id_den, rate_num, ent, smooth};
    #pragma unroll
    for (int i = 0; i < 7; i++) {
        float v = vals[i];
        #pragma unroll
        for (int off = 16; off > 0; off >>= 1)
            v += __shfl_down_sync(0xffffffffu, v, off);
        if (lane == 0) wpart[i][warp] = v;
    }
    __syncthreads();   // also completes agg[] scatter

    if (tid == 0) {
        float s = 0.f, PmSum = 0.f;
        int Ucnt = 0;
        #pragma unroll 4
        for (int u = 0; u < U2_; u++) {
            s += agg[u];
            PmSum += Pm[u];
            if (tbl[ids_s[u]] == u) Ucnt++;
        }
        const float invS  = 1.f / fmaxf(s, EPSF);
        const float uni   = 1.f / fmaxf((float)Ucnt, 1.f);
        const float invPm = 1.f / fmaxf(PmSum, EPSF);
        float kl = 0.f;
        for (int u = 0; u < U2_; u++) {
            if (tbl[ids_s[u]] != u) continue;
            float Pb  = (s > 0.f) ? agg[u] * invS : uni;
            float Pbc = fmaxf(Pb, EPSF);
            float Pmn = fmaxf(Pm[u] * invPm, EPSF);
            kl += Pbc * (logf(Pbc) - logf(Pmn));
        }

        const int slot_map[7] = {A_SEL_NUM, A_SEL_DEN, A_ID_NUM, A_ID_DEN,
                                 A_RATE, A_ENT, A_SMOOTH};
        #pragma unroll
        for (int i = 0; i < 7; i++) {
            float v = wpart[i][0] + wpart[i][1] + wpart[i][2] + wpart[i][3] +
                      wpart[i][4] + wpart[i][5] + wpart[i][6] + wpart[i][7];
            g_part[slot_map[i] * BS_ + b] = v;
        }
        g_part[A_KL  * BS_ + b] = kl;
        g_part[A_LEN * BS_ + b] = (float)(len - 2);

        g_cnt[b] = 0;                // reset for next graph replay
        __threadfence();             // release g_part writes
        s_fin = (atomicAdd(&g_done, 1u) == BS_ - 1) ? 1u : 0u;
    }
    __syncthreads();
    if (!s_fin) return;

    // ============ Phase 3: final combine (last batch arriver) ============
    if (tid == 0) { __threadfence(); g_done = 0; }
    __syncthreads();

    // reuse wpart-like reduction: 9 slots x 256 batches
    __shared__ float wsum[NACC][8];
    #pragma unroll
    for (int s = 0; s < NACC; s++) {
        float v = g_part[s * BS_ + tid];
        #pragma unroll
        for (int off = 16; off > 0; off >>= 1)
            v += __shfl_down_sync(0xffffffffu, v, off);
        if (lane == 0) wsum[s][warp] = v;
    }
    __syncthreads();

    if (tid == 0) {
        float acc[NACC];
        #pragma unroll
        for (int s = 0; s < NACC; s++)
            acc[s] = wsum[s][0] + wsum[s][1] + wsum[s][2] + wsum[s][3] +
                     wsum[s][4] + wsum[s][5] + wsum[s][6] + wsum[s][7];

        float loss_sel    = acc[A_SEL_NUM] / fmaxf(acc[A_SEL_DEN], 1.f);
        float loss_id     = 10.f * acc[A_ID_NUM] / fmaxf(acc[A_ID_DEN], 1.f);
        float loss_rate   = 5.f * acc[A_RATE] / fmaxf(acc[A_LEN], 1.f);
        float loss_kl     = 0.1f * acc[A_KL] / (float)BS_;
        float loss_ent    = 0.05f * 0.5f * acc[A_ENT] / (float)BS_;
        float loss_smooth = 0.5f * acc[A_SMOOTH];
        d_out[0] = loss_sel + loss_id + loss_rate + loss_kl + loss_ent + loss_smooth;
    }
}

// ---------------------------------------------------------------------------
extern "C" void kernel_launch(void* const* d_in, const int* in_sizes, int n_in,
                              void* d_out, int out_size) {
    // metadata order: selector_logits, selector_probs, selector_onehot,
    // out_ids, out_rates, trg_labels, trg_rates, trg_lengths, candi_ids, routes
    const float* sel_probs   = (const float*)d_in[1];
    const float* sel_onehot  = (const float*)d_in[2];
    const float* out_ids     = (const float*)d_in[3];
    const float* out_rates   = (const float*)d_in[4];
    const float* trg_labels  = (const float*)d_in[5];
    const float* trg_rates   = (const float*)d_in[6];
    const int*   trg_lengths = (const int*)d_in[7];
    const int*   candi_ids   = (const int*)d_in[8];
    const int*   routes      = (const int*)d_in[9];

    dim3 grid(NCHUNK, BS_);
    fused_loss<<<grid, 256>>>(out_ids, trg_labels, candi_ids, sel_probs,
                              routes, sel_onehot, out_rates, trg_rates,
                              trg_lengths, (float*)d_out);
}